// round 1
// baseline (speedup 1.0000x reference)
#include <cuda_runtime.h>
#include <cstdint>

#define N_NODES 6144
#define HEADS 4
#define FH 64
#define FIN 512
#define NCLS 40
#define MAX_DEG 128

// ---------------- device scratch (static, no allocation) ----------------
__device__ int   g_col[N_NODES * MAX_DEG];          // neighbor column ids (ELL)
__device__ int   g_len[N_NODES];                    // degree per row
__device__ float g_Wh[HEADS * N_NODES * FH];        // per-head projected features
__device__ float g_f1[HEADS * N_NODES];             // source scores
__device__ float g_f2[HEADS * N_NODES];             // dest scores
__device__ float g_hcat[N_NODES * HEADS * FH];      // concat'd ELU(head outputs)
__device__ float g_Who[N_NODES * NCLS];             // output-layer projected feats
__device__ float g_f1o[N_NODES];
__device__ float g_f2o[N_NODES];

// ---------------- helpers ----------------
__device__ __forceinline__ float warpMax(float v) {
#pragma unroll
    for (int o = 16; o; o >>= 1) v = fmaxf(v, __shfl_xor_sync(0xffffffffu, v, o));
    return v;
}
__device__ __forceinline__ float warpSum(float v) {
#pragma unroll
    for (int o = 16; o; o >>= 1) v += __shfl_xor_sync(0xffffffffu, v, o);
    return v;
}
__device__ __forceinline__ float lrelu(float x) { return x > 0.f ? x : 0.2f * x; }
__device__ __forceinline__ float elu(float x) { return x > 0.f ? x : (expf(x) - 1.f); }

// ---------------- 1) build ELL adjacency: warp per row ----------------
__global__ void build_csr_kernel(const float* __restrict__ adj) {
    int gw = (blockIdx.x * blockDim.x + threadIdx.x) >> 5;
    int lane = threadIdx.x & 31;
    if (gw >= N_NODES) return;
    const float4* row = reinterpret_cast<const float4*>(adj + (size_t)gw * N_NODES);
    int* out = g_col + (size_t)gw * MAX_DEG;
    int count = 0;
    // 6144/4 = 1536 float4 per row, 32 lanes -> 48 iterations
    for (int base = 0; base < N_NODES / 4; base += 32) {
        float4 v = row[base + lane];
        int c0 = v.x > 0.f, c1 = v.y > 0.f, c2 = v.z > 0.f, c3 = v.w > 0.f;
        int local = c0 + c1 + c2 + c3;
        // inclusive prefix across lanes
        int pre = local;
#pragma unroll
        for (int off = 1; off < 32; off <<= 1) {
            int n = __shfl_up_sync(0xffffffffu, pre, off);
            if (lane >= off) pre += n;
        }
        int pos = count + (pre - local);
        int col0 = (base + lane) * 4;
        if (c0) { if (pos < MAX_DEG) out[pos] = col0;     pos++; }
        if (c1) { if (pos < MAX_DEG) out[pos] = col0 + 1; pos++; }
        if (c2) { if (pos < MAX_DEG) out[pos] = col0 + 2; pos++; }
        if (c3) { if (pos < MAX_DEG) out[pos] = col0 + 3; pos++; }
        count += __shfl_sync(0xffffffffu, pre, 31);
    }
    if (lane == 0) g_len[gw] = count < MAX_DEG ? count : MAX_DEG;
}

// ---------------- 2) Wh = x @ W (all heads fused, 6144x512 @ 512x256) ----------------
__global__ __launch_bounds__(256) void gemm_wh_kernel(
    const float* __restrict__ x, const float* __restrict__ W) {
    __shared__ float As[16][65];   // [k][m], padded
    __shared__ float Bs[16][64];   // [k][c]
    int head = blockIdx.x;         // 64-wide n-tile == one head
    int m0 = blockIdx.y * 64;
    int tid = threadIdx.x;
    const float* Wp = W + (size_t)head * FIN * FH;

    int tx = tid & 15;   // col quad
    int ty = tid >> 4;   // row quad
    float acc[4][4] = {};

    int la_m = tid >> 2;            // 0..63
    int la_k = (tid & 3) * 4;       // 0,4,8,12
    int lb_k = tid >> 4;            // 0..15
    int lb_c = (tid & 15) * 4;      // 0..60

    for (int k0 = 0; k0 < FIN; k0 += 16) {
        float4 av = *reinterpret_cast<const float4*>(x + (size_t)(m0 + la_m) * FIN + k0 + la_k);
        float4 bv = *reinterpret_cast<const float4*>(Wp + (size_t)(k0 + lb_k) * FH + lb_c);
        As[la_k + 0][la_m] = av.x;
        As[la_k + 1][la_m] = av.y;
        As[la_k + 2][la_m] = av.z;
        As[la_k + 3][la_m] = av.w;
        *reinterpret_cast<float4*>(&Bs[lb_k][lb_c]) = bv;
        __syncthreads();
#pragma unroll
        for (int k = 0; k < 16; k++) {
            float a[4], b[4];
#pragma unroll
            for (int j = 0; j < 4; j++) a[j] = As[k][ty * 4 + j];
#pragma unroll
            for (int j = 0; j < 4; j++) b[j] = Bs[k][tx * 4 + j];
#pragma unroll
            for (int i = 0; i < 4; i++)
#pragma unroll
                for (int j = 0; j < 4; j++) acc[i][j] += a[i] * b[j];
        }
        __syncthreads();
    }
#pragma unroll
    for (int i = 0; i < 4; i++) {
        float4 v = make_float4(acc[i][0], acc[i][1], acc[i][2], acc[i][3]);
        *reinterpret_cast<float4*>(
            &g_Wh[((size_t)head * N_NODES + m0 + ty * 4 + i) * FH + tx * 4]) = v;
    }
}

// ---------------- 3) f1/f2 per (head,node): warp per row ----------------
__global__ void compute_f_kernel(const float* __restrict__ a1, const float* __restrict__ a2) {
    int gw = (blockIdx.x * blockDim.x + threadIdx.x) >> 5;
    int lane = threadIdx.x & 31;
    if (gw >= HEADS * N_NODES) return;
    int h = gw / N_NODES;
    const float* r = g_Wh + (size_t)gw * FH;
    float w0 = r[lane], w1 = r[lane + 32];
    float v1 = w0 * a1[h * FH + lane] + w1 * a1[h * FH + lane + 32];
    float v2 = w0 * a2[h * FH + lane] + w1 * a2[h * FH + lane + 32];
    v1 = warpSum(v1);
    v2 = warpSum(v2);
    if (lane == 0) { g_f1[gw] = v1; g_f2[gw] = v2; }
}

// ---------------- 4) sparse attention per head + ELU + concat ----------------
__global__ void attn_heads_kernel() {
    int gw = (blockIdx.x * blockDim.x + threadIdx.x) >> 5;
    int lane = threadIdx.x & 31;
    if (gw >= HEADS * N_NODES) return;
    int h = gw / N_NODES;
    int i = gw - h * N_NODES;
    int len = g_len[i];
    const int* cols = g_col + (size_t)i * MAX_DEG;
    float f1i = g_f1[gw];
    const float* f2h = g_f2 + (size_t)h * N_NODES;

    float m = -1e30f;
    for (int t = lane; t < len; t += 32) {
        float e = lrelu(f1i + f2h[cols[t]]);
        m = fmaxf(m, e);
    }
    m = warpMax(m);
    float s = 0.f;
    for (int t = lane; t < len; t += 32) {
        float e = lrelu(f1i + f2h[cols[t]]);
        s += expf(e - m);
    }
    s = warpSum(s);
    float inv = 1.f / s;

    const float* WhH = g_Wh + (size_t)h * N_NODES * FH;
    float acc0 = 0.f, acc1 = 0.f;
    for (int t = 0; t < len; t++) {
        int j = cols[t];                              // broadcast
        float w = expf(lrelu(f1i + f2h[j]) - m) * inv;
        const float* wr = WhH + (size_t)j * FH;
        acc0 += w * wr[lane];
        acc1 += w * wr[lane + 32];
    }
    acc0 = elu(acc0);
    acc1 = elu(acc1);
    g_hcat[(size_t)i * (HEADS * FH) + h * FH + lane] = acc0;
    g_hcat[(size_t)i * (HEADS * FH) + h * FH + 32 + lane] = acc1;
}

// ---------------- 5) Who = hcat @ Wo, fused f1o/f2o: warp per row ----------------
__global__ __launch_bounds__(256) void out_proj_kernel(
    const float* __restrict__ Wo, const float* __restrict__ ao1,
    const float* __restrict__ ao2) {
    __shared__ float sWo[(HEADS * FH) * NCLS];  // 256*40 = 10240 floats = 40KB
    for (int t = threadIdx.x; t < (HEADS * FH) * NCLS; t += blockDim.x) sWo[t] = Wo[t];
    __syncthreads();
    int warp = threadIdx.x >> 5, lane = threadIdx.x & 31;
    int i = blockIdx.x * 8 + warp;
    const float* hr = g_hcat + (size_t)i * (HEADS * FH);
    bool hi = lane < (NCLS - 32);
    float acc0 = 0.f, acc1 = 0.f;
    for (int k0 = 0; k0 < HEADS * FH; k0 += 32) {
        float hv = hr[k0 + lane];
#pragma unroll
        for (int kk = 0; kk < 32; kk++) {
            float hb = __shfl_sync(0xffffffffu, hv, kk);
            const float* wrow = sWo + (k0 + kk) * NCLS;
            acc0 += hb * wrow[lane];
            if (hi) acc1 += hb * wrow[32 + lane];
        }
    }
    g_Who[(size_t)i * NCLS + lane] = acc0;
    if (hi) g_Who[(size_t)i * NCLS + 32 + lane] = acc1;
    float v1 = acc0 * ao1[lane] + (hi ? acc1 * ao1[32 + lane] : 0.f);
    float v2 = acc0 * ao2[lane] + (hi ? acc1 * ao2[32 + lane] : 0.f);
    v1 = warpSum(v1);
    v2 = warpSum(v2);
    if (lane == 0) { g_f1o[i] = v1; g_f2o[i] = v2; }
}

// ---------------- 6) output sparse attention + ELU + log_softmax ----------------
__global__ void attn_out_kernel(float* __restrict__ out) {
    int gw = (blockIdx.x * blockDim.x + threadIdx.x) >> 5;
    int lane = threadIdx.x & 31;
    if (gw >= N_NODES) return;
    int i = gw;
    int len = g_len[i];
    const int* cols = g_col + (size_t)i * MAX_DEG;
    float f1i = g_f1o[i];

    float m = -1e30f;
    for (int t = lane; t < len; t += 32) {
        float e = lrelu(f1i + g_f2o[cols[t]]);
        m = fmaxf(m, e);
    }
    m = warpMax(m);
    float s = 0.f;
    for (int t = lane; t < len; t += 32) {
        float e = lrelu(f1i + g_f2o[cols[t]]);
        s += expf(e - m);
    }
    s = warpSum(s);
    float inv = 1.f / s;

    bool hi = lane < (NCLS - 32);
    float acc0 = 0.f, acc1 = 0.f;
    for (int t = 0; t < len; t++) {
        int j = cols[t];
        float w = expf(lrelu(f1i + g_f2o[j]) - m) * inv;
        const float* wr = g_Who + (size_t)j * NCLS;
        acc0 += w * wr[lane];
        if (hi) acc1 += w * wr[32 + lane];
    }
    float v0 = elu(acc0);
    float v1 = hi ? elu(acc1) : -1e30f;
    float mm = warpMax(fmaxf(v0, v1));
    float se = expf(v0 - mm) + (hi ? expf(v1 - mm) : 0.f);
    se = warpSum(se);
    float lse = logf(se);
    out[(size_t)i * NCLS + lane] = v0 - mm - lse;
    if (hi) out[(size_t)i * NCLS + 32 + lane] = v1 - mm - lse;
}

// ---------------- launch ----------------
extern "C" void kernel_launch(void* const* d_in, const int* in_sizes, int n_in,
                              void* d_out, int out_size) {
    const float* x   = (const float*)d_in[0];   // [6144, 512]
    const float* adj = (const float*)d_in[1];   // [6144, 6144]
    const float* W   = (const float*)d_in[2];   // [4, 512, 64]
    const float* a1  = (const float*)d_in[3];   // [4, 64]
    const float* a2  = (const float*)d_in[4];   // [4, 64]
    const float* Wo  = (const float*)d_in[5];   // [256, 40]
    const float* ao1 = (const float*)d_in[6];   // [40]
    const float* ao2 = (const float*)d_in[7];   // [40]
    float* out = (float*)d_out;                 // [6144, 40]

    (void)in_sizes; (void)n_in; (void)out_size;

    build_csr_kernel<<<N_NODES / 8, 256>>>(adj);
    gemm_wh_kernel<<<dim3(HEADS, N_NODES / 64), 256>>>(x, W);
    compute_f_kernel<<<HEADS * N_NODES / 8, 256>>>(a1, a2);
    attn_heads_kernel<<<HEADS * N_NODES / 8, 256>>>();
    out_proj_kernel<<<N_NODES / 8, 256>>>(Wo, ao1, ao2);
    attn_out_kernel<<<N_NODES / 8, 256>>>(out);
}

// round 2
// speedup vs baseline: 1.1817x; 1.1817x over previous
#include <cuda_runtime.h>
#include <cstdint>

#define N_NODES 6144
#define HEADS 4
#define FH 64
#define FIN 512
#define NCLS 40
#define MAX_DEG 128
#define GEMM_BLOCKS 192   // 48 m-tiles (128 rows) x 4 heads (64-wide n-tile)
#define CSR_BLOCKS 192    // 8 warps/block, 4 rows/warp -> 6144 rows

// ---------------- device scratch (static, no allocation) ----------------
__device__ int   g_col[N_NODES * MAX_DEG];
__device__ int   g_len[N_NODES];
__device__ float g_Wh[HEADS * N_NODES * FH];
__device__ float g_f1[HEADS * N_NODES];
__device__ float g_f2[HEADS * N_NODES];
__device__ float g_hcat[N_NODES * HEADS * FH];
__device__ float g_Who[N_NODES * NCLS];
__device__ float g_f1o[N_NODES];
__device__ float g_f2o[N_NODES];

// ---------------- helpers ----------------
__device__ __forceinline__ float warpMax(float v) {
#pragma unroll
    for (int o = 16; o; o >>= 1) v = fmaxf(v, __shfl_xor_sync(0xffffffffu, v, o));
    return v;
}
__device__ __forceinline__ float warpSum(float v) {
#pragma unroll
    for (int o = 16; o; o >>= 1) v += __shfl_xor_sync(0xffffffffu, v, o);
    return v;
}
__device__ __forceinline__ float lrelu(float x) { return x > 0.f ? x : 0.2f * x; }
__device__ __forceinline__ float elu(float x) { return x > 0.f ? x : (expf(x) - 1.f); }

// ============ K1: fused adjacency-compaction + GEMM(Wh) + f1/f2 ============
__global__ __launch_bounds__(256) void fused_prep_kernel(
    const float* __restrict__ x, const float* __restrict__ W,
    const float* __restrict__ a1, const float* __restrict__ a2,
    const float* __restrict__ adj) {
    int b = blockIdx.x;
    if (b < GEMM_BLOCKS) {
        // ---- GEMM path: Wh[head] tile (128 x 64), K = 512 ----
        __shared__ float As[16][132];
        __shared__ float Bs[16][64];
        int head = b & 3;
        int m0 = (b >> 2) * 128;
        int tid = threadIdx.x;
        const float* Wp = W + (size_t)head * FIN * FH;
        int tx = tid & 15, ty = tid >> 4;
        float acc[8][4] = {};
        int la_m = tid >> 2;            // 0..63
        int la_k = (tid & 3) * 4;       // 0,4,8,12
        int lb_k = tid >> 4;            // 0..15
        int lb_c = (tid & 15) * 4;      // 0..60
        const float* xA = x + (size_t)(m0 + la_m) * FIN + la_k;
        const float* xB = x + (size_t)(m0 + la_m + 64) * FIN + la_k;

        for (int k0 = 0; k0 < FIN; k0 += 16) {
            float4 av0 = *reinterpret_cast<const float4*>(xA + k0);
            float4 av1 = *reinterpret_cast<const float4*>(xB + k0);
            float4 bv  = *reinterpret_cast<const float4*>(Wp + (size_t)(k0 + lb_k) * FH + lb_c);
            As[la_k + 0][la_m] = av0.x;
            As[la_k + 1][la_m] = av0.y;
            As[la_k + 2][la_m] = av0.z;
            As[la_k + 3][la_m] = av0.w;
            As[la_k + 0][la_m + 64] = av1.x;
            As[la_k + 1][la_m + 64] = av1.y;
            As[la_k + 2][la_m + 64] = av1.z;
            As[la_k + 3][la_m + 64] = av1.w;
            *reinterpret_cast<float4*>(&Bs[lb_k][lb_c]) = bv;
            __syncthreads();
#pragma unroll
            for (int k = 0; k < 16; k++) {
                float a[8], bb[4];
                *reinterpret_cast<float4*>(a)     = *reinterpret_cast<const float4*>(&As[k][ty * 8]);
                *reinterpret_cast<float4*>(a + 4) = *reinterpret_cast<const float4*>(&As[k][ty * 8 + 4]);
                *reinterpret_cast<float4*>(bb)    = *reinterpret_cast<const float4*>(&Bs[k][tx * 4]);
#pragma unroll
                for (int i = 0; i < 8; i++)
#pragma unroll
                    for (int j = 0; j < 4; j++) acc[i][j] += a[i] * bb[j];
            }
            __syncthreads();
        }
        // epilogue: store Wh + fused f1/f2 row dot-products
        float a1v[4], a2v[4];
#pragma unroll
        for (int j = 0; j < 4; j++) {
            a1v[j] = a1[head * FH + tx * 4 + j];
            a2v[j] = a2[head * FH + tx * 4 + j];
        }
#pragma unroll
        for (int i = 0; i < 8; i++) {
            int row = m0 + ty * 8 + i;
            float4 v = make_float4(acc[i][0], acc[i][1], acc[i][2], acc[i][3]);
            *reinterpret_cast<float4*>(&g_Wh[((size_t)head * N_NODES + row) * FH + tx * 4]) = v;
            float p1 = acc[i][0] * a1v[0] + acc[i][1] * a1v[1] + acc[i][2] * a1v[2] + acc[i][3] * a1v[3];
            float p2 = acc[i][0] * a2v[0] + acc[i][1] * a2v[1] + acc[i][2] * a2v[2] + acc[i][3] * a2v[3];
#pragma unroll
            for (int off = 8; off; off >>= 1) {
                p1 += __shfl_down_sync(0xffffffffu, p1, off, 16);
                p2 += __shfl_down_sync(0xffffffffu, p2, off, 16);
            }
            if (tx == 0) {
                g_f1[head * N_NODES + row] = p1;
                g_f2[head * N_NODES + row] = p2;
            }
        }
    } else {
        // ---- CSR path: warp per 4 rows, ballot compaction, MLP-4 loads ----
        int warp = threadIdx.x >> 5, lane = threadIdx.x & 31;
        int wid = (b - GEMM_BLOCKS) * 8 + warp;   // 0..1535
        unsigned lt = (1u << lane) - 1u;
        for (int rr = 0; rr < 4; rr++) {
            int row = wid * 4 + rr;
            const float4* rp = reinterpret_cast<const float4*>(adj + (size_t)row * N_NODES);
            int* outp = g_col + (size_t)row * MAX_DEG;
            int count = 0;
            for (int it = 0; it < N_NODES / 128; it += 4) {  // 48 iters, 4 at a time
                float4 v[4];
#pragma unroll
                for (int u = 0; u < 4; u++) v[u] = rp[(it + u) * 32 + lane];
#pragma unroll
                for (int u = 0; u < 4; u++) {
                    float4 vv = v[u];
                    int c0 = vv.x > 0.f, c1 = vv.y > 0.f, c2 = vv.z > 0.f, c3 = vv.w > 0.f;
                    unsigned m0b = __ballot_sync(0xffffffffu, c0);
                    unsigned m1b = __ballot_sync(0xffffffffu, c1);
                    unsigned m2b = __ballot_sync(0xffffffffu, c2);
                    unsigned m3b = __ballot_sync(0xffffffffu, c3);
                    int before = __popc(m0b & lt) + __popc(m1b & lt) + __popc(m2b & lt) + __popc(m3b & lt);
                    int pos = count + before;
                    int col0 = ((it + u) * 32 + lane) * 4;
                    if (c0) { if (pos < MAX_DEG) outp[pos] = col0;     pos++; }
                    if (c1) { if (pos < MAX_DEG) outp[pos] = col0 + 1; pos++; }
                    if (c2) { if (pos < MAX_DEG) outp[pos] = col0 + 2; pos++; }
                    if (c3) { if (pos < MAX_DEG) outp[pos] = col0 + 3; pos++; }
                    count += __popc(m0b) + __popc(m1b) + __popc(m2b) + __popc(m3b);
                }
            }
            if (lane == 0) g_len[row] = count < MAX_DEG ? count : MAX_DEG;
        }
    }
}

// ============ K2: sparse attention per head + ELU + concat ============
__global__ __launch_bounds__(256) void attn_heads_kernel() {
    __shared__ float sw[8][MAX_DEG];
    __shared__ int   sc[8][MAX_DEG];
    int warp = threadIdx.x >> 5, lane = threadIdx.x & 31;
    int h = blockIdx.y;
    int i = blockIdx.x * 8 + warp;
    int len = g_len[i];
    const int* cols = g_col + (size_t)i * MAX_DEG;
    float f1i = g_f1[h * N_NODES + i];
    const float* f2h = g_f2 + (size_t)h * N_NODES;

    float m = -1e30f;
    for (int t = lane; t < len; t += 32) {
        int j = __ldg(cols + t);
        sc[warp][t] = j;
        float e = lrelu(f1i + f2h[j]);
        sw[warp][t] = e;
        m = fmaxf(m, e);
    }
    m = warpMax(m);
    float s = 0.f;
    for (int t = lane; t < len; t += 32) {
        float we = expf(sw[warp][t] - m);
        sw[warp][t] = we;
        s += we;
    }
    s = warpSum(s);
    float inv = 1.f / s;
    __syncwarp();

    const float* WhH = g_Wh + (size_t)h * N_NODES * FH;
    float accA[4] = {0.f, 0.f, 0.f, 0.f}, accB[4] = {0.f, 0.f, 0.f, 0.f};
    int t = 0;
    for (; t + 4 <= len; t += 4) {
#pragma unroll
        for (int u = 0; u < 4; u++) {
            int j = sc[warp][t + u];
            float wgt = sw[warp][t + u];
            const float* wr = WhH + (size_t)j * FH;
            accA[u] += wgt * wr[lane];
            accB[u] += wgt * wr[lane + 32];
        }
    }
    for (; t < len; t++) {
        int j = sc[warp][t];
        float wgt = sw[warp][t];
        const float* wr = WhH + (size_t)j * FH;
        accA[0] += wgt * wr[lane];
        accB[0] += wgt * wr[lane + 32];
    }
    float r0 = elu((accA[0] + accA[1] + accA[2] + accA[3]) * inv);
    float r1 = elu((accB[0] + accB[1] + accB[2] + accB[3]) * inv);
    g_hcat[(size_t)i * (HEADS * FH) + h * FH + lane] = r0;
    g_hcat[(size_t)i * (HEADS * FH) + h * FH + 32 + lane] = r1;
}

// ============ K3: Who = hcat @ Wo, fused f1o/f2o ============
__global__ __launch_bounds__(256) void out_proj_kernel(
    const float* __restrict__ Wo, const float* __restrict__ ao1,
    const float* __restrict__ ao2) {
    __shared__ float sWo[(HEADS * FH) * NCLS];  // 40 KB
    for (int t = threadIdx.x; t < (HEADS * FH) * NCLS; t += blockDim.x) sWo[t] = Wo[t];
    __syncthreads();
    int warp = threadIdx.x >> 5, lane = threadIdx.x & 31;
    int i = blockIdx.x * 8 + warp;
    const float* hr = g_hcat + (size_t)i * (HEADS * FH);
    bool hi = lane < (NCLS - 32);
    float acc0 = 0.f, acc1 = 0.f;
    for (int k0 = 0; k0 < HEADS * FH; k0 += 32) {
        float hv = hr[k0 + lane];
#pragma unroll
        for (int kk = 0; kk < 32; kk++) {
            float hb = __shfl_sync(0xffffffffu, hv, kk);
            const float* wrow = sWo + (k0 + kk) * NCLS;
            acc0 += hb * wrow[lane];
            if (hi) acc1 += hb * wrow[32 + lane];
        }
    }
    g_Who[(size_t)i * NCLS + lane] = acc0;
    if (hi) g_Who[(size_t)i * NCLS + 32 + lane] = acc1;
    float v1 = acc0 * ao1[lane] + (hi ? acc1 * ao1[32 + lane] : 0.f);
    float v2 = acc0 * ao2[lane] + (hi ? acc1 * ao2[32 + lane] : 0.f);
    v1 = warpSum(v1);
    v2 = warpSum(v2);
    if (lane == 0) { g_f1o[i] = v1; g_f2o[i] = v2; }
}

// ============ K4: output sparse attention + ELU + log_softmax ============
__global__ __launch_bounds__(256) void attn_out_kernel(float* __restrict__ out) {
    __shared__ float sw[8][MAX_DEG];
    __shared__ int   sc[8][MAX_DEG];
    int warp = threadIdx.x >> 5, lane = threadIdx.x & 31;
    int i = blockIdx.x * 8 + warp;
    int len = g_len[i];
    const int* cols = g_col + (size_t)i * MAX_DEG;
    float f1i = g_f1o[i];

    float m = -1e30f;
    for (int t = lane; t < len; t += 32) {
        int j = __ldg(cols + t);
        sc[warp][t] = j;
        float e = lrelu(f1i + g_f2o[j]);
        sw[warp][t] = e;
        m = fmaxf(m, e);
    }
    m = warpMax(m);
    float s = 0.f;
    for (int t = lane; t < len; t += 32) {
        float we = expf(sw[warp][t] - m);
        sw[warp][t] = we;
        s += we;
    }
    s = warpSum(s);
    float inv = 1.f / s;
    __syncwarp();

    bool hi = lane < (NCLS - 32);
    float accA[4] = {0.f, 0.f, 0.f, 0.f};
    float accB[2] = {0.f, 0.f};
    int t = 0;
    for (; t + 4 <= len; t += 4) {
#pragma unroll
        for (int u = 0; u < 4; u++) {
            int j = sc[warp][t + u];
            float wgt = sw[warp][t + u];
            const float* wr = g_Who + (size_t)j * NCLS;
            accA[u] += wgt * wr[lane];
            if (hi) accB[u & 1] += wgt * wr[32 + lane];
        }
    }
    for (; t < len; t++) {
        int j = sc[warp][t];
        float wgt = sw[warp][t];
        const float* wr = g_Who + (size_t)j * NCLS;
        accA[0] += wgt * wr[lane];
        if (hi) accB[0] += wgt * wr[32 + lane];
    }
    float v0 = elu((accA[0] + accA[1] + accA[2] + accA[3]) * inv);
    float v1 = hi ? elu((accB[0] + accB[1]) * inv) : -1e30f;
    float mm = warpMax(fmaxf(v0, v1));
    float se = expf(v0 - mm) + (hi ? expf(v1 - mm) : 0.f);
    se = warpSum(se);
    float lse = logf(se);
    out[(size_t)i * NCLS + lane] = v0 - mm - lse;
    if (hi) out[(size_t)i * NCLS + 32 + lane] = v1 - mm - lse;
}

// ---------------- launch ----------------
extern "C" void kernel_launch(void* const* d_in, const int* in_sizes, int n_in,
                              void* d_out, int out_size) {
    const float* x   = (const float*)d_in[0];
    const float* adj = (const float*)d_in[1];
    const float* W   = (const float*)d_in[2];
    const float* a1  = (const float*)d_in[3];
    const float* a2  = (const float*)d_in[4];
    const float* Wo  = (const float*)d_in[5];
    const float* ao1 = (const float*)d_in[6];
    const float* ao2 = (const float*)d_in[7];
    float* out = (float*)d_out;
    (void)in_sizes; (void)n_in; (void)out_size;

    fused_prep_kernel<<<GEMM_BLOCKS + CSR_BLOCKS, 256>>>(x, W, a1, a2, adj);
    attn_heads_kernel<<<dim3(N_NODES / 8, HEADS), 256>>>();
    out_proj_kernel<<<N_NODES / 8, 256>>>(Wo, ao1, ao2);
    attn_out_kernel<<<N_NODES / 8, 256>>>(out);
}